// round 16
// baseline (speedup 1.0000x reference)
#include <cuda_runtime.h>
#include <cuda_bf16.h>
#include <cstdint>

#define BB 32
#define TT 128
#define EE 256
#define HH 1024
#define VV 32000
#define ZN 4096          // 4*H
#define NBLK 148         // persistent grid size (<= SM count, co-resident)

typedef unsigned long long ull;

// ---------------- device scratch (static, allocation-free) ----------------
__device__ __align__(16) float g_zx[(size_t)TT * BB * ZN];   // x@W1x + b1, row = t*32+b
__device__ __align__(16) float g_h1[BB * HH];
__device__ __align__(16) float g_c1[BB * HH];
__device__ __align__(16) float g_h2[BB * HH];
__device__ __align__(16) float g_c2[BB * HH];
__device__ __align__(16) float g_z1p[4 * BB * ZN];           // layer1 K-split partials
__device__ __align__(16) float g_z2p[8 * BB * ZN];           // layer2 K-split partials

// logits A operand (h2 history as bf16 hi/lo), row = b*T+t
__device__ __align__(16) __nv_bfloat16 g_Ahi[(size_t)BB * TT * HH];
__device__ __align__(16) __nv_bfloat16 g_Alo[(size_t)BB * TT * HH];

// logits weights hi/lo [VV][HH]
__device__ __align__(16) __nv_bfloat16 g_Whi[(size_t)VV * HH];
__device__ __align__(16) __nv_bfloat16 g_Wlo[(size_t)VV * HH];

// contention-free barrier state: per-block epoch flags + release word
__device__ unsigned int g_flags[NBLK];
__device__ unsigned int g_gen;

// ---------------- f32x2 helpers ----------------
__device__ __forceinline__ ull pack2(float x, float y) {
    ull r; asm("mov.b64 %0, {%1, %2};" : "=l"(r) : "f"(x), "f"(y)); return r;
}
__device__ __forceinline__ ull fma2(ull a, ull b, ull c) {
    ull d; asm("fma.rn.f32x2 %0, %1, %2, %3;" : "=l"(d) : "l"(a), "l"(b), "l"(c)); return d;
}
__device__ __forceinline__ float2 unpack2(ull v) {
    float2 r; asm("mov.b64 {%0, %1}, %2;" : "=f"(r.x), "=f"(r.y) : "l"(v)); return r;
}

// ---------------- base-ISA tensor helpers (logits kernel) ----------------
__device__ __forceinline__ uint32_t smem_u32(const void* p) {
    uint32_t a;
    asm("{ .reg .u64 t; cvta.to.shared.u64 t, %1; cvt.u32.u64 %0, t; }" : "=r"(a) : "l"(p));
    return a;
}
#define SWZ128(off) ((off) ^ (((off) >> 3) & 0x70))
#define CP_ASYNC16(saddr, gaddr) \
    asm volatile("cp.async.cg.shared.global [%0], [%1], 16;" :: "r"(saddr), "l"(gaddr))
#define CP_COMMIT() asm volatile("cp.async.commit_group;" ::: "memory")
#define CP_WAIT0()  asm volatile("cp.async.wait_group 0;" ::: "memory")
#define LDSM_X4(r0, r1, r2, r3, addr) \
    asm volatile("ldmatrix.sync.aligned.m8n8.x4.shared.b16 {%0,%1,%2,%3}, [%4];" \
        : "=r"(r0), "=r"(r1), "=r"(r2), "=r"(r3) : "r"(addr))
#define MMA16816(d, a, b) \
    asm volatile("mma.sync.aligned.m16n8k16.row.col.f32.bf16.bf16.f32 " \
        "{%0,%1,%2,%3}, {%4,%5,%6,%7}, {%8,%9}, {%0,%1,%2,%3};" \
        : "+f"((d)[0]), "+f"((d)[1]), "+f"((d)[2]), "+f"((d)[3]) \
        : "r"((a)[0]), "r"((a)[1]), "r"((a)[2]), "r"((a)[3]), "r"((b)[0]), "r"((b)[1]))

// ---------------- grid-wide barrier (flag-array, atomic-free) ----------------
// Arrival: each block's thread 0 stores its epoch to a private flag (no contention).
// Block 0: threads 0..NBLK-1 poll the flags IN PARALLEL, then thread 0 releases.
// Epochs are monotonic within a launch; zx_kernel resets state for graph replay.
__device__ __forceinline__ void grid_bar(unsigned int target) {
    __syncthreads();
    const int bid = blockIdx.x, tid = threadIdx.x;
    if (tid == 0) {
        __threadfence();
        asm volatile("st.release.gpu.u32 [%0], %1;" :: "l"(&g_flags[bid]), "r"(target) : "memory");
    }
    if (bid == 0) {
        if (tid < NBLK) {
            unsigned int v;
            do {
                asm volatile("ld.acquire.gpu.u32 %0, [%1];" : "=r"(v) : "l"(&g_flags[tid]) : "memory");
            } while (v < target);
        }
        __syncthreads();
        if (tid == 0) {
            asm volatile("st.release.gpu.u32 [%0], %1;" :: "l"(&g_gen), "r"(target) : "memory");
        }
    } else {
        if (tid == 0) {
            unsigned int v;
            do {
                asm volatile("ld.acquire.gpu.u32 %0, [%1];" : "=r"(v) : "l"(&g_gen) : "memory");
            } while (v < target);
        }
        __syncthreads();
    }
}

// ============================================================================
// zx precompute: g_zx[t*32+b][n] = b1[n] + emb[ids[b][t]] @ W1[0:256]
// Also resets barrier state (required: graph replays re-run the whole launch).
// ============================================================================
__global__ void __launch_bounds__(256) zx_kernel(const int* __restrict__ ids,
                                                 const float* __restrict__ emb,
                                                 const float* __restrict__ W1,
                                                 const float* __restrict__ b1) {
    if (blockIdx.x == 0 && blockIdx.y == 0) {
        if (threadIdx.x < NBLK) g_flags[threadIdx.x] = 0u;
        if (threadIdx.x == 0) g_gen = 0u;
    }
    __shared__ __align__(16) float a_s[16 * 68];
    __shared__ __align__(16) float w_s[16 * 68];

    const int tid  = threadIdx.x;
    const int m0   = blockIdx.y * 64;
    const int n0   = blockIdx.x * 64;
    const int srow = tid >> 2;
    const int skq  = (tid & 3) * 4;
    const int wk   = tid >> 4;
    const int wn   = (tid & 15) * 4;
    const int ty   = tid >> 4;
    const int tx   = tid & 15;

    const int r  = m0 + srow;
    const int bb = r & 31;
    const int tt = r >> 5;
    const float* arow = emb + (size_t)ids[bb * TT + tt] * EE + skq;

    ull acc[4][2];
    #pragma unroll
    for (int i = 0; i < 4; i++) { acc[i][0] = 0ULL; acc[i][1] = 0ULL; }

    for (int k0 = 0; k0 < EE; k0 += 16) {
        float4 av = *reinterpret_cast<const float4*>(arow + k0);
        a_s[(skq + 0) * 68 + srow] = av.x;
        a_s[(skq + 1) * 68 + srow] = av.y;
        a_s[(skq + 2) * 68 + srow] = av.z;
        a_s[(skq + 3) * 68 + srow] = av.w;
        *reinterpret_cast<float4*>(w_s + wk * 68 + wn) =
            *reinterpret_cast<const float4*>(W1 + (size_t)(k0 + wk) * ZN + n0 + wn);
        __syncthreads();
        #pragma unroll
        for (int k = 0; k < 16; k++) {
            float4 a = *reinterpret_cast<const float4*>(a_s + k * 68 + ty * 4);
            ulonglong2 w = *reinterpret_cast<const ulonglong2*>(w_s + k * 68 + tx * 4);
            ull ax = pack2(a.x, a.x), ay = pack2(a.y, a.y);
            ull az = pack2(a.z, a.z), aw = pack2(a.w, a.w);
            acc[0][0] = fma2(ax, w.x, acc[0][0]); acc[0][1] = fma2(ax, w.y, acc[0][1]);
            acc[1][0] = fma2(ay, w.x, acc[1][0]); acc[1][1] = fma2(ay, w.y, acc[1][1]);
            acc[2][0] = fma2(az, w.x, acc[2][0]); acc[2][1] = fma2(az, w.y, acc[2][1]);
            acc[3][0] = fma2(aw, w.x, acc[3][0]); acc[3][1] = fma2(aw, w.y, acc[3][1]);
        }
        __syncthreads();
    }

    float4 bv = *reinterpret_cast<const float4*>(b1 + n0 + tx * 4);
    #pragma unroll
    for (int i = 0; i < 4; i++) {
        float2 r0 = unpack2(acc[i][0]);
        float2 r1 = unpack2(acc[i][1]);
        float4 o;
        o.x = r0.x + bv.x; o.y = r0.y + bv.y;
        o.z = r1.x + bv.z; o.w = r1.y + bv.w;
        *reinterpret_cast<float4*>(g_zx + (size_t)(m0 + ty * 4 + i) * ZN + n0 + tx * 4) = o;
    }
}

// ============================================================================
// fp32 f32x2 GEMM task (R4-proven): pout[32][n0:n0+128] = hsrc[32][0:256] @ wrow
// ============================================================================
__device__ __forceinline__ void gemm_task(const float* __restrict__ hsrc,
                                          const float* __restrict__ wrow,
                                          float* __restrict__ pout, int n0,
                                          float* a_s /*32x36*/, float* w_s /*32x128*/) {
    const int tid = threadIdx.x;
    const int sb  = tid >> 3;
    const int skq = (tid & 7) << 2;
    const int tx  = tid & 31;
    const int bq  = tid >> 5;
    const float* ap = hsrc + (size_t)sb * HH + skq;

    ull acc[4][2];
    #pragma unroll
    for (int i = 0; i < 4; i++) { acc[i][0] = 0ULL; acc[i][1] = 0ULL; }

    float4 pa = *reinterpret_cast<const float4*>(ap);
    float4 pw[4];
    #pragma unroll
    for (int j = 0; j < 4; j++) {
        int idx = tid + j * 256, row = idx >> 5, c4 = (idx & 31) << 2;
        pw[j] = *reinterpret_cast<const float4*>(wrow + (size_t)row * ZN + n0 + c4);
    }

    for (int kt = 0; kt < 256; kt += 32) {
        a_s[(skq + 0) * 36 + sb] = pa.x;
        a_s[(skq + 1) * 36 + sb] = pa.y;
        a_s[(skq + 2) * 36 + sb] = pa.z;
        a_s[(skq + 3) * 36 + sb] = pa.w;
        #pragma unroll
        for (int j = 0; j < 4; j++) {
            int idx = tid + j * 256, row = idx >> 5, c4 = (idx & 31) << 2;
            *reinterpret_cast<float4*>(w_s + row * 128 + c4) = pw[j];
        }
        __syncthreads();
        if (kt + 32 < 256) {
            pa = *reinterpret_cast<const float4*>(ap + kt + 32);
            #pragma unroll
            for (int j = 0; j < 4; j++) {
                int idx = tid + j * 256, row = idx >> 5, c4 = (idx & 31) << 2;
                pw[j] = *reinterpret_cast<const float4*>(wrow + (size_t)(kt + 32 + row) * ZN + n0 + c4);
            }
        }
        #pragma unroll
        for (int k = 0; k < 32; k++) {
            float4 a = *reinterpret_cast<const float4*>(a_s + k * 36 + (bq << 2));
            ulonglong2 w = *reinterpret_cast<const ulonglong2*>(w_s + k * 128 + (tx << 2));
            ull ax = pack2(a.x, a.x), ay = pack2(a.y, a.y);
            ull az = pack2(a.z, a.z), aw = pack2(a.w, a.w);
            acc[0][0] = fma2(ax, w.x, acc[0][0]); acc[0][1] = fma2(ax, w.y, acc[0][1]);
            acc[1][0] = fma2(ay, w.x, acc[1][0]); acc[1][1] = fma2(ay, w.y, acc[1][1]);
            acc[2][0] = fma2(az, w.x, acc[2][0]); acc[2][1] = fma2(az, w.y, acc[2][1]);
            acc[3][0] = fma2(aw, w.x, acc[3][0]); acc[3][1] = fma2(aw, w.y, acc[3][1]);
        }
        __syncthreads();
    }

    #pragma unroll
    for (int i = 0; i < 4; i++) {
        float2 r0 = unpack2(acc[i][0]);
        float2 r1 = unpack2(acc[i][1]);
        float4 o; o.x = r0.x; o.y = r0.y; o.z = r1.x; o.w = r1.y;
        *reinterpret_cast<float4*>(pout + (size_t)((bq << 2) + i) * ZN + n0 + (tx << 2)) = o;
    }
}

__device__ __forceinline__ float sigf(float x) { return 1.f / (1.f + expf(-x)); }

__device__ __forceinline__ void gates1_work(int t, int start, int stride) {
    for (int idx = start; idx < BB * HH; idx += stride) {
        int b = idx >> 10, n = idx & (HH - 1);
        const float* zx = g_zx + ((size_t)t * BB + b) * ZN;
        float zi = zx[n], zj = zx[HH + n], zf = zx[2 * HH + n], zo = zx[3 * HH + n];
        #pragma unroll
        for (int kc = 0; kc < 4; kc++) {
            const float* p = g_z1p + ((size_t)kc * BB + b) * ZN;
            zi += p[n]; zj += p[HH + n]; zf += p[2 * HH + n]; zo += p[3 * HH + n];
        }
        float cn = g_c1[idx] * sigf(zf) + sigf(zi) * tanhf(zj);
        g_c1[idx] = cn;
        g_h1[idx] = tanhf(cn) * sigf(zo);
    }
}

__device__ __forceinline__ void gates2_work(int t, const float* __restrict__ b2,
                                            int start, int stride) {
    for (int idx = start; idx < BB * HH; idx += stride) {
        int b = idx >> 10, n = idx & (HH - 1);
        float zi = b2[n], zj = b2[HH + n], zf = b2[2 * HH + n], zo = b2[3 * HH + n];
        #pragma unroll
        for (int kc = 0; kc < 8; kc++) {
            const float* p = g_z2p + ((size_t)kc * BB + b) * ZN;
            zi += p[n]; zj += p[HH + n]; zf += p[2 * HH + n]; zo += p[3 * HH + n];
        }
        float cn = g_c2[idx] * sigf(zf) + sigf(zi) * tanhf(zj);
        g_c2[idx] = cn;
        float hn = tanhf(cn) * sigf(zo);
        g_h2[idx] = hn;
        __nv_bfloat16 hi = __float2bfloat16_rn(hn);
        __nv_bfloat16 lo = __float2bfloat16_rn(hn - __bfloat162float(hi));
        size_t hrow = ((size_t)b * TT + t) * HH + n;
        g_Ahi[hrow] = hi;
        g_Alo[hrow] = lo;
    }
}

// ============================================================================
// Persistent LSTM — 2 phases/step (R14-proven schedule):
//  X(t): blocks 0..127 run three gemm_tasks: l1(t)[h1(t-1)],
//        l2-h1half(t-1)[h1(t-1)], l2-h2half(t-1)[h2(t-2)].      BAR
//  Y(t): gates1(t) + gates2(t-1) on all blocks.                  BAR
// ============================================================================
__global__ void __launch_bounds__(256) lstm_kernel(const float* __restrict__ W1,
                                                   const float* __restrict__ W2,
                                                   const float* __restrict__ b2) {
    __shared__ __align__(16) float a_s[32 * 36];
    __shared__ __align__(16) float w_s[32 * 128];
    unsigned int bar = 0;
    const int bid = blockIdx.x, tid = threadIdx.x;

    for (int i = bid * 256 + tid; i < BB * HH; i += NBLK * 256) {
        g_h1[i] = 0.f; g_c1[i] = 0.f; g_h2[i] = 0.f; g_c2[i] = 0.f;
    }
    grid_bar(++bar);

    const int ntile = bid & 31;
    const int kc    = bid >> 5;     // 0..3 for bid<128
    const int n0    = ntile * 128;
    const int gid   = bid * 256 + tid;

    for (int t = 0; t < TT; t++) {
        // ---- X(t): all GEMM work for gates1(t) and gates2(t-1)
        if (bid < 128) {
            gemm_task(g_h1 + kc * 256,
                      W1 + (size_t)(EE + kc * 256) * ZN,
                      g_z1p + (size_t)kc * BB * ZN,
                      n0, a_s, w_s);
            if (t > 0) {
                gemm_task(g_h1 + kc * 256,
                          W2 + (size_t)kc * 256 * ZN,
                          g_z2p + (size_t)kc * BB * ZN,
                          n0, a_s, w_s);
                gemm_task(g_h2 + kc * 256,
                          W2 + (size_t)(kc + 4) * 256 * ZN,
                          g_z2p + (size_t)(kc + 4) * BB * ZN,
                          n0, a_s, w_s);
            }
        }
        grid_bar(++bar);

        // ---- Y(t): gates on all blocks
        gates1_work(t, gid, NBLK * 256);
        if (t > 0) gates2_work(t - 1, b2, gid, NBLK * 256);
        grid_bar(++bar);
    }

    // tail: layer2 GEMM for step TT-1, then gates2(TT-1)
    if (bid < 128) {
        gemm_task(g_h1 + kc * 256,
                  W2 + (size_t)kc * 256 * ZN,
                  g_z2p + (size_t)kc * BB * ZN,
                  n0, a_s, w_s);
        gemm_task(g_h2 + kc * 256,
                  W2 + (size_t)(kc + 4) * 256 * ZN,
                  g_z2p + (size_t)(kc + 4) * BB * ZN,
                  n0, a_s, w_s);
    }
    grid_bar(++bar);
    gates2_work(TT - 1, b2, gid, NBLK * 256);
}

// ============================================================================
// bf16 hi/lo split for logits weights
// ============================================================================
__global__ void __launch_bounds__(256) conv_w_kernel(const float* __restrict__ Wv) {
    size_t i = (size_t)blockIdx.x * 256 + threadIdx.x;
    float4 v = reinterpret_cast<const float4*>(Wv)[i];
    __nv_bfloat16 h0 = __float2bfloat16_rn(v.x), h1 = __float2bfloat16_rn(v.y);
    __nv_bfloat16 h2 = __float2bfloat16_rn(v.z), h3 = __float2bfloat16_rn(v.w);
    __nv_bfloat16 l0 = __float2bfloat16_rn(v.x - __bfloat162float(h0));
    __nv_bfloat16 l1 = __float2bfloat16_rn(v.y - __bfloat162float(h1));
    __nv_bfloat16 l2 = __float2bfloat16_rn(v.z - __bfloat162float(h2));
    __nv_bfloat16 l3 = __float2bfloat16_rn(v.w - __bfloat162float(h3));
    __nv_bfloat162 hp0 = {h0, h1}, hp1 = {h2, h3}, lp0 = {l0, l1}, lp1 = {l2, l3};
    uint2 hi, lo;
    hi.x = *reinterpret_cast<uint32_t*>(&hp0); hi.y = *reinterpret_cast<uint32_t*>(&hp1);
    lo.x = *reinterpret_cast<uint32_t*>(&lp0); lo.y = *reinterpret_cast<uint32_t*>(&lp1);
    reinterpret_cast<uint2*>(g_Whi)[i] = hi;
    reinterpret_cast<uint2*>(g_Wlo)[i] = lo;
}

// ============================================================================
// HMMA logits GEMM: out[4096][32000] = hs @ Wv^T + sb  (bf16x3 split)
// BM=64 (was 128): smem 2x48K, ~regs halved -> 2 CTAs/SM co-resident.
// 8 warps = (wm 0..1: 32 M-rows) x (wn 0..3: 32 N-cols).
// ============================================================================
#define LSTAGE 49152                 // Ahi 8K | Alo 8K | Whi 16K | Wlo 16K
#define LSMEM_TOTAL (2 * LSTAGE)     // 98304

__global__ void __launch_bounds__(256) logits_hmma_kernel(const float* __restrict__ sbias,
                                                          float* __restrict__ out) {
    extern __shared__ __align__(1024) char smem[];
    const uint32_t sb32 = smem_u32(smem);
    const int tid  = threadIdx.x;
    const int wid  = tid >> 5, lane = tid & 31;
    const int m0   = blockIdx.x * 64;
    const int v0   = blockIdx.y * 128;
    const int wm   = wid >> 2;        // 0..1
    const int wn   = wid & 3;         // 0..3

    const int r8  = tid >> 3;
    const int l16 = (tid & 7) * 16;

    const char* pAhi = reinterpret_cast<const char*>(g_Ahi);
    const char* pAlo = reinterpret_cast<const char*>(g_Alo);
    const char* pWhi = reinterpret_cast<const char*>(g_Whi);
    const char* pWlo = reinterpret_cast<const char*>(g_Wlo);

    auto stage = [&](int c) {
        const uint32_t sb = sb32 + (c & 1) * LSTAGE;
        #pragma unroll
        for (int rr = 0; rr < 2; rr++) {           // A: 64 rows
            int row = rr * 32 + r8;
            size_t goffA = (size_t)(m0 + row) * (HH * 2) + c * 128 + l16;
            uint32_t soff = SWZ128((uint32_t)(row * 128 + l16));
            CP_ASYNC16(sb + soff,        pAhi + goffA);
            CP_ASYNC16(sb + 8192 + soff, pAlo + goffA);
        }
        #pragma unroll
        for (int rr = 0; rr < 4; rr++) {           // W: 128 rows
            int row = rr * 32 + r8;
            size_t goffW = (size_t)(v0 + row) * (HH * 2) + c * 128 + l16;
            uint32_t soff = SWZ128((uint32_t)(row * 128 + l16));
            CP_ASYNC16(sb + 16384 + soff, pWhi + goffW);
            CP_ASYNC16(sb + 32768 + soff, pWlo + goffW);
        }
        CP_COMMIT();
    };

    float acc[2][4][4];
    #pragma unroll
    for (int mt = 0; mt < 2; mt++)
        #pragma unroll
        for (int nt = 0; nt < 4; nt++)
            #pragma unroll
            for (int j = 0; j < 4; j++) acc[mt][nt][j] = 0.f;

    stage(0);

    const int a_row = wm * 32 + (lane & 15);
    const int a_kbs = ((lane >> 4) & 1) * 16;
    const int b_row = wn * 32 + ((lane >> 4) & 1) * 8 + (lane & 7);
    const int b_kbs = ((lane >> 3) & 1) * 16;

    for (int c = 0; c < 16; c++) {
        CP_WAIT0();
        __syncthreads();
        if (c < 15) stage(c + 1);

        const uint32_t sb = sb32 + (c & 1) * LSTAGE;
        #pragma unroll
        for (int ks = 0; ks < 4; ks++) {
            uint32_t ahi[2][4], alo[2][4];
            #pragma unroll
            for (int mt = 0; mt < 2; mt++) {
                uint32_t off = SWZ128((uint32_t)((a_row + mt * 16) * 128 + ks * 32 + a_kbs));
                LDSM_X4(ahi[mt][0], ahi[mt][1], ahi[mt][2], ahi[mt][3], sb + off);
                LDSM_X4(alo[mt][0], alo[mt][1], alo[mt][2], alo[mt][3], sb + 8192 + off);
            }
            uint32_t bhi[4][2], blo[4][2];
            #pragma unroll
            for (int p = 0; p < 2; p++) {
                uint32_t off = SWZ128((uint32_t)((b_row + p * 16) * 128 + ks * 32 + b_kbs));
                LDSM_X4(bhi[2 * p][0], bhi[2 * p][1], bhi[2 * p + 1][0], bhi[2 * p + 1][1],
                        sb + 16384 + off);
                LDSM_X4(blo[2 * p][0], blo[2 * p][1], blo[2 * p + 1][0], blo[2 * p + 1][1],
                        sb + 32768 + off);
            }
            #pragma unroll
            for (int mt = 0; mt < 2; mt++)
                #pragma unroll
                for (int nt = 0; nt < 4; nt++) {
                    MMA16816(acc[mt][nt], ahi[mt], bhi[nt]);
                    MMA16816(acc[mt][nt], ahi[mt], blo[nt]);
                    MMA16816(acc[mt][nt], alo[mt], bhi[nt]);
                }
        }
        __syncthreads();
    }

    #pragma unroll
    for (int mt = 0; mt < 2; mt++) {
        int row = m0 + wm * 32 + mt * 16 + (lane >> 2);
        #pragma unroll
        for (int nt = 0; nt < 4; nt++) {
            int col = v0 + wn * 32 + nt * 8 + (lane & 3) * 2;
            float2 bv = *reinterpret_cast<const float2*>(sbias + col);
            float2 o0, o1;
            o0.x = acc[mt][nt][0] + bv.x; o0.y = acc[mt][nt][1] + bv.y;
            o1.x = acc[mt][nt][2] + bv.x; o1.y = acc[mt][nt][3] + bv.y;
            *reinterpret_cast<float2*>(out + (size_t)row * VV + col)       = o0;
            *reinterpret_cast<float2*>(out + (size_t)(row + 8) * VV + col) = o1;
        }
    }
}

// ---------------- launch ----------------
extern "C" void kernel_launch(void* const* d_in, const int* in_sizes, int n_in,
                              void* d_out, int out_size) {
    const int*   ids = (const int*)d_in[0];     // [B,T] int32
    const float* emb = (const float*)d_in[1];   // [VOCAB,E]
    const float* W1  = (const float*)d_in[2];   // [E+H, 4H]
    const float* b1  = (const float*)d_in[3];   // [4H]
    const float* W2  = (const float*)d_in[4];   // [2H, 4H]
    const float* b2  = (const float*)d_in[5];   // [4H]
    const float* Wv  = (const float*)d_in[6];   // [VOCAB, H]
    const float* sb  = (const float*)d_in[7];   // [VOCAB]
    float* out = (float*)d_out;                 // [B*T, VOCAB]

    cudaFuncSetAttribute(logits_hmma_kernel,
                         cudaFuncAttributeMaxDynamicSharedMemorySize, LSMEM_TOTAL);

    dim3 zxg(ZN / 64, (TT * BB) / 64);
    zx_kernel<<<zxg, 256>>>(ids, emb, W1, b1);

    conv_w_kernel<<<(VV * HH / 4) / 256, 256>>>(Wv);   // independent of lstm

    lstm_kernel<<<NBLK, 256>>>(W1, W2, b2);

    dim3 lg((BB * TT) / 64, VV / 128);   // x = M tiles (64), y = N tiles (250)
    logits_hmma_kernel<<<lg, 256, LSMEM_TOTAL>>>(sb, out);
}

// round 17
// speedup vs baseline: 1.0273x; 1.0273x over previous
#include <cuda_runtime.h>
#include <cuda_bf16.h>
#include <cstdint>

#define BB 32
#define TT 128
#define EE 256
#define HH 1024
#define VV 32000
#define ZN 4096          // 4*H
#define NBLK 148         // persistent grid size (<= SM count, co-resident)

typedef unsigned long long ull;

// ---------------- device scratch (static, allocation-free) ----------------
__device__ __align__(16) float g_zx[(size_t)TT * BB * ZN];   // x@W1x + b1, row = t*32+b
__device__ __align__(16) float g_h1[BB * HH];
__device__ __align__(16) float g_c1[BB * HH];
__device__ __align__(16) float g_h2[BB * HH];
__device__ __align__(16) float g_c2[BB * HH];
__device__ __align__(16) float g_z1p[4 * BB * ZN];           // layer1 K-split partials
__device__ __align__(16) float g_z2p[8 * BB * ZN];           // layer2 K-split partials

// logits A operand (h2 history as bf16 hi/lo), row = b*T+t
__device__ __align__(16) __nv_bfloat16 g_Ahi[(size_t)BB * TT * HH];
__device__ __align__(16) __nv_bfloat16 g_Alo[(size_t)BB * TT * HH];

// logits weights hi/lo [VV][HH]
__device__ __align__(16) __nv_bfloat16 g_Whi[(size_t)VV * HH];
__device__ __align__(16) __nv_bfloat16 g_Wlo[(size_t)VV * HH];

__device__ unsigned int g_arrive;
__device__ unsigned int g_gen;

// ---------------- f32x2 helpers ----------------
__device__ __forceinline__ ull pack2(float x, float y) {
    ull r; asm("mov.b64 %0, {%1, %2};" : "=l"(r) : "f"(x), "f"(y)); return r;
}
__device__ __forceinline__ ull fma2(ull a, ull b, ull c) {
    ull d; asm("fma.rn.f32x2 %0, %1, %2, %3;" : "=l"(d) : "l"(a), "l"(b), "l"(c)); return d;
}
__device__ __forceinline__ float2 unpack2(ull v) {
    float2 r; asm("mov.b64 {%0, %1}, %2;" : "=f"(r.x), "=f"(r.y) : "l"(v)); return r;
}

// ---------------- base-ISA tensor helpers (logits kernel) ----------------
__device__ __forceinline__ uint32_t smem_u32(const void* p) {
    uint32_t a;
    asm("{ .reg .u64 t; cvta.to.shared.u64 t, %1; cvt.u32.u64 %0, t; }" : "=r"(a) : "l"(p));
    return a;
}
#define SWZ128(off) ((off) ^ (((off) >> 3) & 0x70))
#define CP_ASYNC16(saddr, gaddr) \
    asm volatile("cp.async.cg.shared.global [%0], [%1], 16;" :: "r"(saddr), "l"(gaddr))
#define CP_COMMIT() asm volatile("cp.async.commit_group;" ::: "memory")
#define CP_WAIT0()  asm volatile("cp.async.wait_group 0;" ::: "memory")
#define LDSM_X4(r0, r1, r2, r3, addr) \
    asm volatile("ldmatrix.sync.aligned.m8n8.x4.shared.b16 {%0,%1,%2,%3}, [%4];" \
        : "=r"(r0), "=r"(r1), "=r"(r2), "=r"(r3) : "r"(addr))
#define MMA16816(d, a, b) \
    asm volatile("mma.sync.aligned.m16n8k16.row.col.f32.bf16.bf16.f32 " \
        "{%0,%1,%2,%3}, {%4,%5,%6,%7}, {%8,%9}, {%0,%1,%2,%3};" \
        : "+f"((d)[0]), "+f"((d)[1]), "+f"((d)[2]), "+f"((d)[3]) \
        : "r"((a)[0]), "r"((a)[1]), "r"((a)[2]), "r"((a)[3]), "r"((b)[0]), "r"((b)[1]))

// ---------------- grid-wide barrier (R14-proven atomic version) ----------------
__device__ __forceinline__ void grid_bar(unsigned int target) {
    __syncthreads();
    if (threadIdx.x == 0) {
        __threadfence();
        unsigned int old = atomicAdd(&g_arrive, 1u);
        if (old == gridDim.x - 1) {
            atomicExch(&g_arrive, 0u);
            asm volatile("st.release.gpu.u32 [%0], %1;" :: "l"(&g_gen), "r"(target) : "memory");
        } else {
            unsigned int cur;
            do {
                asm volatile("ld.acquire.gpu.u32 %0, [%1];" : "=r"(cur) : "l"(&g_gen) : "memory");
            } while (cur < target);
        }
    }
    __syncthreads();
}

// ============================================================================
// zx precompute: g_zx[t*32+b][n] = b1[n] + emb[ids[b][t]] @ W1[0:256]
// ============================================================================
__global__ void __launch_bounds__(256) zx_kernel(const int* __restrict__ ids,
                                                 const float* __restrict__ emb,
                                                 const float* __restrict__ W1,
                                                 const float* __restrict__ b1) {
    if (blockIdx.x == 0 && blockIdx.y == 0 && threadIdx.x == 0) {
        g_arrive = 0u;
        g_gen = 0u;
    }
    __shared__ __align__(16) float a_s[16 * 68];
    __shared__ __align__(16) float w_s[16 * 68];

    const int tid  = threadIdx.x;
    const int m0   = blockIdx.y * 64;
    const int n0   = blockIdx.x * 64;
    const int srow = tid >> 2;
    const int skq  = (tid & 3) * 4;
    const int wk   = tid >> 4;
    const int wn   = (tid & 15) * 4;
    const int ty   = tid >> 4;
    const int tx   = tid & 15;

    const int r  = m0 + srow;
    const int bb = r & 31;
    const int tt = r >> 5;
    const float* arow = emb + (size_t)ids[bb * TT + tt] * EE + skq;

    ull acc[4][2];
    #pragma unroll
    for (int i = 0; i < 4; i++) { acc[i][0] = 0ULL; acc[i][1] = 0ULL; }

    for (int k0 = 0; k0 < EE; k0 += 16) {
        float4 av = *reinterpret_cast<const float4*>(arow + k0);
        a_s[(skq + 0) * 68 + srow] = av.x;
        a_s[(skq + 1) * 68 + srow] = av.y;
        a_s[(skq + 2) * 68 + srow] = av.z;
        a_s[(skq + 3) * 68 + srow] = av.w;
        *reinterpret_cast<float4*>(w_s + wk * 68 + wn) =
            *reinterpret_cast<const float4*>(W1 + (size_t)(k0 + wk) * ZN + n0 + wn);
        __syncthreads();
        #pragma unroll
        for (int k = 0; k < 16; k++) {
            float4 a = *reinterpret_cast<const float4*>(a_s + k * 68 + ty * 4);
            ulonglong2 w = *reinterpret_cast<const ulonglong2*>(w_s + k * 68 + tx * 4);
            ull ax = pack2(a.x, a.x), ay = pack2(a.y, a.y);
            ull az = pack2(a.z, a.z), aw = pack2(a.w, a.w);
            acc[0][0] = fma2(ax, w.x, acc[0][0]); acc[0][1] = fma2(ax, w.y, acc[0][1]);
            acc[1][0] = fma2(ay, w.x, acc[1][0]); acc[1][1] = fma2(ay, w.y, acc[1][1]);
            acc[2][0] = fma2(az, w.x, acc[2][0]); acc[2][1] = fma2(az, w.y, acc[2][1]);
            acc[3][0] = fma2(aw, w.x, acc[3][0]); acc[3][1] = fma2(aw, w.y, acc[3][1]);
        }
        __syncthreads();
    }

    float4 bv = *reinterpret_cast<const float4*>(b1 + n0 + tx * 4);
    #pragma unroll
    for (int i = 0; i < 4; i++) {
        float2 r0 = unpack2(acc[i][0]);
        float2 r1 = unpack2(acc[i][1]);
        float4 o;
        o.x = r0.x + bv.x; o.y = r0.y + bv.y;
        o.z = r1.x + bv.z; o.w = r1.y + bv.w;
        *reinterpret_cast<float4*>(g_zx + (size_t)(m0 + ty * 4 + i) * ZN + n0 + tx * 4) = o;
    }
}

// ============================================================================
// fp32 f32x2 GEMM task (R4-proven): pout[32][n0:n0+128] = hsrc[32][0:256] @ wrow
// ============================================================================
__device__ __forceinline__ void gemm_task(const float* __restrict__ hsrc,
                                          const float* __restrict__ wrow,
                                          float* __restrict__ pout, int n0,
                                          float* a_s /*32x36*/, float* w_s /*32x128*/) {
    const int tid = threadIdx.x;
    const int sb  = tid >> 3;
    const int skq = (tid & 7) << 2;
    const int tx  = tid & 31;
    const int bq  = tid >> 5;
    const float* ap = hsrc + (size_t)sb * HH + skq;

    ull acc[4][2];
    #pragma unroll
    for (int i = 0; i < 4; i++) { acc[i][0] = 0ULL; acc[i][1] = 0ULL; }

    float4 pa = *reinterpret_cast<const float4*>(ap);
    float4 pw[4];
    #pragma unroll
    for (int j = 0; j < 4; j++) {
        int idx = tid + j * 256, row = idx >> 5, c4 = (idx & 31) << 2;
        pw[j] = *reinterpret_cast<const float4*>(wrow + (size_t)row * ZN + n0 + c4);
    }

    for (int kt = 0; kt < 256; kt += 32) {
        a_s[(skq + 0) * 36 + sb] = pa.x;
        a_s[(skq + 1) * 36 + sb] = pa.y;
        a_s[(skq + 2) * 36 + sb] = pa.z;
        a_s[(skq + 3) * 36 + sb] = pa.w;
        #pragma unroll
        for (int j = 0; j < 4; j++) {
            int idx = tid + j * 256, row = idx >> 5, c4 = (idx & 31) << 2;
            *reinterpret_cast<float4*>(w_s + row * 128 + c4) = pw[j];
        }
        __syncthreads();
        if (kt + 32 < 256) {
            pa = *reinterpret_cast<const float4*>(ap + kt + 32);
            #pragma unroll
            for (int j = 0; j < 4; j++) {
                int idx = tid + j * 256, row = idx >> 5, c4 = (idx & 31) << 2;
                pw[j] = *reinterpret_cast<const float4*>(wrow + (size_t)(kt + 32 + row) * ZN + n0 + c4);
            }
        }
        #pragma unroll
        for (int k = 0; k < 32; k++) {
            float4 a = *reinterpret_cast<const float4*>(a_s + k * 36 + (bq << 2));
            ulonglong2 w = *reinterpret_cast<const ulonglong2*>(w_s + k * 128 + (tx << 2));
            ull ax = pack2(a.x, a.x), ay = pack2(a.y, a.y);
            ull az = pack2(a.z, a.z), aw = pack2(a.w, a.w);
            acc[0][0] = fma2(ax, w.x, acc[0][0]); acc[0][1] = fma2(ax, w.y, acc[0][1]);
            acc[1][0] = fma2(ay, w.x, acc[1][0]); acc[1][1] = fma2(ay, w.y, acc[1][1]);
            acc[2][0] = fma2(az, w.x, acc[2][0]); acc[2][1] = fma2(az, w.y, acc[2][1]);
            acc[3][0] = fma2(aw, w.x, acc[3][0]); acc[3][1] = fma2(aw, w.y, acc[3][1]);
        }
        __syncthreads();
    }

    #pragma unroll
    for (int i = 0; i < 4; i++) {
        float2 r0 = unpack2(acc[i][0]);
        float2 r1 = unpack2(acc[i][1]);
        float4 o; o.x = r0.x; o.y = r0.y; o.z = r1.x; o.w = r1.y;
        *reinterpret_cast<float4*>(pout + (size_t)((bq << 2) + i) * ZN + n0 + (tx << 2)) = o;
    }
}

__device__ __forceinline__ float sigf(float x) { return 1.f / (1.f + expf(-x)); }

__device__ __forceinline__ void gates1_work(int t, int start, int stride) {
    for (int idx = start; idx < BB * HH; idx += stride) {
        int b = idx >> 10, n = idx & (HH - 1);
        const float* zx = g_zx + ((size_t)t * BB + b) * ZN;
        float zi = zx[n], zj = zx[HH + n], zf = zx[2 * HH + n], zo = zx[3 * HH + n];
        #pragma unroll
        for (int kc = 0; kc < 4; kc++) {
            const float* p = g_z1p + ((size_t)kc * BB + b) * ZN;
            zi += p[n]; zj += p[HH + n]; zf += p[2 * HH + n]; zo += p[3 * HH + n];
        }
        float cn = g_c1[idx] * sigf(zf) + sigf(zi) * tanhf(zj);
        g_c1[idx] = cn;
        g_h1[idx] = tanhf(cn) * sigf(zo);
    }
}

__device__ __forceinline__ void gates2_work(int t, const float* __restrict__ b2,
                                            int start, int stride) {
    for (int idx = start; idx < BB * HH; idx += stride) {
        int b = idx >> 10, n = idx & (HH - 1);
        float zi = b2[n], zj = b2[HH + n], zf = b2[2 * HH + n], zo = b2[3 * HH + n];
        #pragma unroll
        for (int kc = 0; kc < 8; kc++) {
            const float* p = g_z2p + ((size_t)kc * BB + b) * ZN;
            zi += p[n]; zj += p[HH + n]; zf += p[2 * HH + n]; zo += p[3 * HH + n];
        }
        float cn = g_c2[idx] * sigf(zf) + sigf(zi) * tanhf(zj);
        g_c2[idx] = cn;
        float hn = tanhf(cn) * sigf(zo);
        g_h2[idx] = hn;
        __nv_bfloat16 hi = __float2bfloat16_rn(hn);
        __nv_bfloat16 lo = __float2bfloat16_rn(hn - __bfloat162float(hi));
        size_t hrow = ((size_t)b * TT + t) * HH + n;
        g_Ahi[hrow] = hi;
        g_Alo[hrow] = lo;
    }
}

// ============================================================================
// Persistent LSTM — 2 phases/step (R14-proven schedule):
//  X(t): blocks 0..127 run three gemm_tasks: l1(t)[h1(t-1)],
//        l2-h1half(t-1)[h1(t-1)], l2-h2half(t-1)[h2(t-2)].      BAR
//  Y(t): gates1(t) + gates2(t-1) on all blocks.                  BAR
// ============================================================================
__global__ void __launch_bounds__(256) lstm_kernel(const float* __restrict__ W1,
                                                   const float* __restrict__ W2,
                                                   const float* __restrict__ b2) {
    __shared__ __align__(16) float a_s[32 * 36];
    __shared__ __align__(16) float w_s[32 * 128];
    unsigned int bar = 0;
    const int bid = blockIdx.x, tid = threadIdx.x;

    for (int i = bid * 256 + tid; i < BB * HH; i += NBLK * 256) {
        g_h1[i] = 0.f; g_c1[i] = 0.f; g_h2[i] = 0.f; g_c2[i] = 0.f;
    }
    grid_bar(++bar);

    const int ntile = bid & 31;
    const int kc    = bid >> 5;     // 0..3 for bid<128
    const int n0    = ntile * 128;
    const int gid   = bid * 256 + tid;

    for (int t = 0; t < TT; t++) {
        // ---- X(t): all GEMM work for gates1(t) and gates2(t-1)
        if (bid < 128) {
            gemm_task(g_h1 + kc * 256,
                      W1 + (size_t)(EE + kc * 256) * ZN,
                      g_z1p + (size_t)kc * BB * ZN,
                      n0, a_s, w_s);
            if (t > 0) {
                gemm_task(g_h1 + kc * 256,
                          W2 + (size_t)kc * 256 * ZN,
                          g_z2p + (size_t)kc * BB * ZN,
                          n0, a_s, w_s);
                gemm_task(g_h2 + kc * 256,
                          W2 + (size_t)(kc + 4) * 256 * ZN,
                          g_z2p + (size_t)(kc + 4) * BB * ZN,
                          n0, a_s, w_s);
            }
        }
        grid_bar(++bar);

        // ---- Y(t): gates on all blocks
        gates1_work(t, gid, NBLK * 256);
        if (t > 0) gates2_work(t - 1, b2, gid, NBLK * 256);
        grid_bar(++bar);
    }

    // tail: layer2 GEMM for step TT-1, then gates2(TT-1)
    if (bid < 128) {
        gemm_task(g_h1 + kc * 256,
                  W2 + (size_t)kc * 256 * ZN,
                  g_z2p + (size_t)kc * BB * ZN,
                  n0, a_s, w_s);
        gemm_task(g_h2 + kc * 256,
                  W2 + (size_t)(kc + 4) * 256 * ZN,
                  g_z2p + (size_t)(kc + 4) * BB * ZN,
                  n0, a_s, w_s);
    }
    grid_bar(++bar);
    gates2_work(TT - 1, b2, gid, NBLK * 256);
}

// ============================================================================
// bf16 hi/lo split for logits weights
// ============================================================================
__global__ void __launch_bounds__(256) conv_w_kernel(const float* __restrict__ Wv) {
    size_t i = (size_t)blockIdx.x * 256 + threadIdx.x;
    float4 v = reinterpret_cast<const float4*>(Wv)[i];
    __nv_bfloat16 h0 = __float2bfloat16_rn(v.x), h1 = __float2bfloat16_rn(v.y);
    __nv_bfloat16 h2 = __float2bfloat16_rn(v.z), h3 = __float2bfloat16_rn(v.w);
    __nv_bfloat16 l0 = __float2bfloat16_rn(v.x - __bfloat162float(h0));
    __nv_bfloat16 l1 = __float2bfloat16_rn(v.y - __bfloat162float(h1));
    __nv_bfloat16 l2 = __float2bfloat16_rn(v.z - __bfloat162float(h2));
    __nv_bfloat16 l3 = __float2bfloat16_rn(v.w - __bfloat162float(h3));
    __nv_bfloat162 hp0 = {h0, h1}, hp1 = {h2, h3}, lp0 = {l0, l1}, lp1 = {l2, l3};
    uint2 hi, lo;
    hi.x = *reinterpret_cast<uint32_t*>(&hp0); hi.y = *reinterpret_cast<uint32_t*>(&hp1);
    lo.x = *reinterpret_cast<uint32_t*>(&lp0); lo.y = *reinterpret_cast<uint32_t*>(&lp1);
    reinterpret_cast<uint2*>(g_Whi)[i] = hi;
    reinterpret_cast<uint2*>(g_Wlo)[i] = lo;
}

// ============================================================================
// HMMA logits GEMM: out[4096][32000] = hs @ Wv^T + sb  (bf16x3 split)
// BM=64: smem 2x48K, regs ~94 -> 2 CTAs/SM co-resident (R15-proven).
// 8 warps = (wm 0..1: 32 M-rows) x (wn 0..3: 32 N-cols).
// ============================================================================
#define LSTAGE 49152                 // Ahi 8K | Alo 8K | Whi 16K | Wlo 16K
#define LSMEM_TOTAL (2 * LSTAGE)     // 98304

__global__ void __launch_bounds__(256) logits_hmma_kernel(const float* __restrict__ sbias,
                                                          float* __restrict__ out) {
    extern __shared__ __align__(1024) char smem[];
    const uint32_t sb32 = smem_u32(smem);
    const int tid  = threadIdx.x;
    const int wid  = tid >> 5, lane = tid & 31;
    const int m0   = blockIdx.x * 64;
    const int v0   = blockIdx.y * 128;
    const int wm   = wid >> 2;        // 0..1
    const int wn   = wid & 3;         // 0..3

    const int r8  = tid >> 3;
    const int l16 = (tid & 7) * 16;

    const char* pAhi = reinterpret_cast<const char*>(g_Ahi);
    const char* pAlo = reinterpret_cast<const char*>(g_Alo);
    const char* pWhi = reinterpret_cast<const char*>(g_Whi);
    const char* pWlo = reinterpret_cast<const char*>(g_Wlo);

    auto stage = [&](int c) {
        const uint32_t sb = sb32 + (c & 1) * LSTAGE;
        #pragma unroll
        for (int rr = 0; rr < 2; rr++) {           // A: 64 rows
            int row = rr * 32 + r8;
            size_t goffA = (size_t)(m0 + row) * (HH * 2) + c * 128 + l16;
            uint32_t soff = SWZ128((uint32_t)(row * 128 + l16));
            CP_ASYNC16(sb + soff,        pAhi + goffA);
            CP_ASYNC16(sb + 8192 + soff, pAlo + goffA);
        }
        #pragma unroll
        for (int rr = 0; rr < 4; rr++) {           // W: 128 rows
            int row = rr * 32 + r8;
            size_t goffW = (size_t)(v0 + row) * (HH * 2) + c * 128 + l16;
            uint32_t soff = SWZ128((uint32_t)(row * 128 + l16));
            CP_ASYNC16(sb + 16384 + soff, pWhi + goffW);
            CP_ASYNC16(sb + 32768 + soff, pWlo + goffW);
        }
        CP_COMMIT();
    };

    float acc[2][4][4];
    #pragma unroll
    for (int mt = 0; mt < 2; mt++)
        #pragma unroll
        for (int nt = 0; nt < 4; nt++)
            #pragma unroll
            for (int j = 0; j < 4; j++) acc[mt][nt][j] = 0.f;

    stage(0);

    const int a_row = wm * 32 + (lane & 15);
    const int a_kbs = ((lane >> 4) & 1) * 16;
    const int b_row = wn * 32 + ((lane >> 4) & 1) * 8 + (lane & 7);
    const int b_kbs = ((lane >> 3) & 1) * 16;

    for (int c = 0; c < 16; c++) {
        CP_WAIT0();
        __syncthreads();
        if (c < 15) stage(c + 1);

        const uint32_t sb = sb32 + (c & 1) * LSTAGE;
        #pragma unroll
        for (int ks = 0; ks < 4; ks++) {
            uint32_t ahi[2][4], alo[2][4];
            #pragma unroll
            for (int mt = 0; mt < 2; mt++) {
                uint32_t off = SWZ128((uint32_t)((a_row + mt * 16) * 128 + ks * 32 + a_kbs));
                LDSM_X4(ahi[mt][0], ahi[mt][1], ahi[mt][2], ahi[mt][3], sb + off);
                LDSM_X4(alo[mt][0], alo[mt][1], alo[mt][2], alo[mt][3], sb + 8192 + off);
            }
            uint32_t bhi[4][2], blo[4][2];
            #pragma unroll
            for (int p = 0; p < 2; p++) {
                uint32_t off = SWZ128((uint32_t)((b_row + p * 16) * 128 + ks * 32 + b_kbs));
                LDSM_X4(bhi[2 * p][0], bhi[2 * p][1], bhi[2 * p + 1][0], bhi[2 * p + 1][1],
                        sb + 16384 + off);
                LDSM_X4(blo[2 * p][0], blo[2 * p][1], blo[2 * p + 1][0], blo[2 * p + 1][1],
                        sb + 32768 + off);
            }
            #pragma unroll
            for (int mt = 0; mt < 2; mt++)
                #pragma unroll
                for (int nt = 0; nt < 4; nt++) {
                    MMA16816(acc[mt][nt], ahi[mt], bhi[nt]);
                    MMA16816(acc[mt][nt], ahi[mt], blo[nt]);
                    MMA16816(acc[mt][nt], alo[mt], bhi[nt]);
                }
        }
        __syncthreads();
    }

    #pragma unroll
    for (int mt = 0; mt < 2; mt++) {
        int row = m0 + wm * 32 + mt * 16 + (lane >> 2);
        #pragma unroll
        for (int nt = 0; nt < 4; nt++) {
            int col = v0 + wn * 32 + nt * 8 + (lane & 3) * 2;
            float2 bv = *reinterpret_cast<const float2*>(sbias + col);
            float2 o0, o1;
            o0.x = acc[mt][nt][0] + bv.x; o0.y = acc[mt][nt][1] + bv.y;
            o1.x = acc[mt][nt][2] + bv.x; o1.y = acc[mt][nt][3] + bv.y;
            *reinterpret_cast<float2*>(out + (size_t)row * VV + col)       = o0;
            *reinterpret_cast<float2*>(out + (size_t)(row + 8) * VV + col) = o1;
        }
    }
}

// ---------------- launch ----------------
extern "C" void kernel_launch(void* const* d_in, const int* in_sizes, int n_in,
                              void* d_out, int out_size) {
    const int*   ids = (const int*)d_in[0];     // [B,T] int32
    const float* emb = (const float*)d_in[1];   // [VOCAB,E]
    const float* W1  = (const float*)d_in[2];   // [E+H, 4H]
    const float* b1  = (const float*)d_in[3];   // [4H]
    const float* W2  = (const float*)d_in[4];   // [2H, 4H]
    const float* b2  = (const float*)d_in[5];   // [4H]
    const float* Wv  = (const float*)d_in[6];   // [VOCAB, H]
    const float* sb  = (const float*)d_in[7];   // [VOCAB]
    float* out = (float*)d_out;                 // [B*T, VOCAB]

    cudaFuncSetAttribute(logits_hmma_kernel,
                         cudaFuncAttributeMaxDynamicSharedMemorySize, LSMEM_TOTAL);

    dim3 zxg(ZN / 64, (TT * BB) / 64);
    zx_kernel<<<zxg, 256>>>(ids, emb, W1, b1);

    conv_w_kernel<<<(VV * HH / 4) / 256, 256>>>(Wv);   // independent of lstm

    lstm_kernel<<<NBLK, 256>>>(W1, W2, b2);

    dim3 lg((BB * TT) / 64, VV / 128);   // x = M tiles (64), y = N tiles (250)
    logits_hmma_kernel<<<lg, 256, LSMEM_TOTAL>>>(sb, out);
}